// round 1
// baseline (speedup 1.0000x reference)
#include <cuda_runtime.h>
#include <cuda_bf16.h>
#include <math.h>

// Problem constants
#define BB 4
#define NN 2048
#define DD 512
#define HH 8
#define HDIM 64
#define MROWS (BB*NN)          // 8192

// ---------------- scratch (static device globals; no runtime allocation) ---
__device__ float g_qkv[MROWS*1536];
__device__ float g_q[MROWS*DD];
__device__ float g_k[MROWS*DD];
__device__ float g_v[MROWS*DD];
__device__ float g_attn[MROWS*DD];
__device__ float g_hcat[MROWS*1024];
__device__ float g_h1[MROWS*1024];

// ---------------------------------------------------------------- SGEMM ----
// C[M,N] = A[M,K] @ B[K,N] + bias (+ res).  Tiles 128x128x8, 256 threads,
// 8x8 microtile per thread.  All dims are multiples of tile sizes here.
__global__ __launch_bounds__(256) void sgemm128(
    const float* __restrict__ A, int lda,
    const float* __restrict__ Bm, int ldb,
    float* __restrict__ C, int ldc,
    const float* __restrict__ bias,
    const float* __restrict__ res, int ldres,
    int K)
{
    __shared__ float As[8][128];
    __shared__ float Bs[8][128];

    const int tid  = threadIdx.x;
    const int brow = blockIdx.y * 128;
    const int bcol = blockIdx.x * 128;
    const int tx   = tid & 15;
    const int ty   = tid >> 4;

    const int arow = tid >> 1;          // 0..127
    const int acol = (tid & 1) * 4;     // 0 or 4
    const int bk   = tid >> 5;          // 0..7
    const int bn   = (tid & 31) * 4;    // 0..124

    float acc[8][8];
    #pragma unroll
    for (int i = 0; i < 8; i++)
        #pragma unroll
        for (int j = 0; j < 8; j++) acc[i][j] = 0.f;

    for (int k0 = 0; k0 < K; k0 += 8) {
        float4 av = *(const float4*)&A[(size_t)(brow + arow) * lda + k0 + acol];
        float4 bv = *(const float4*)&Bm[(size_t)(k0 + bk) * ldb + bcol + bn];
        As[acol + 0][arow] = av.x;
        As[acol + 1][arow] = av.y;
        As[acol + 2][arow] = av.z;
        As[acol + 3][arow] = av.w;
        *(float4*)&Bs[bk][bn] = bv;
        __syncthreads();

        #pragma unroll
        for (int kk = 0; kk < 8; kk++) {
            float a[8], b[8];
            *(float4*)&a[0] = *(const float4*)&As[kk][ty * 4];
            *(float4*)&a[4] = *(const float4*)&As[kk][64 + ty * 4];
            *(float4*)&b[0] = *(const float4*)&Bs[kk][tx * 4];
            *(float4*)&b[4] = *(const float4*)&Bs[kk][64 + tx * 4];
            #pragma unroll
            for (int i = 0; i < 8; i++)
                #pragma unroll
                for (int j = 0; j < 8; j++)
                    acc[i][j] = fmaf(a[i], b[j], acc[i][j]);
        }
        __syncthreads();
    }

    #pragma unroll
    for (int ih = 0; ih < 2; ih++) {
        #pragma unroll
        for (int i = 0; i < 4; i++) {
            int row = brow + ih * 64 + ty * 4 + i;
            #pragma unroll
            for (int jh = 0; jh < 2; jh++) {
                int c = bcol + jh * 64 + tx * 4;
                float4 v;
                v.x = acc[ih*4+i][jh*4+0] + bias[c+0];
                v.y = acc[ih*4+i][jh*4+1] + bias[c+1];
                v.z = acc[ih*4+i][jh*4+2] + bias[c+2];
                v.w = acc[ih*4+i][jh*4+3] + bias[c+3];
                if (res) {
                    const float4 r4 = *(const float4*)&res[(size_t)row * ldres + c];
                    v.x += r4.x; v.y += r4.y; v.z += r4.z; v.w += r4.w;
                }
                *(float4*)&C[(size_t)row * ldc + c] = v;
            }
        }
    }
}

// ------------------------------------------------------------ RoPE split ---
// Reads g_qkv [B,N,3D], applies RoPE to q,k, writes head-major [B,H,N,HD].
__global__ void rope_kernel(const float* __restrict__ freqs)
{
    int idx = blockIdx.x * blockDim.x + threadIdx.x;   // 4*2048*8*32 = 524288
    if (idx >= BB * NN * HH * 32) return;
    int i = idx & 31;
    int h = (idx >> 5) & 7;
    int n = (idx >> 8) & 2047;
    int b = idx >> 19;

    float f = freqs[(b * NN + n) * 32 + i];
    float c = cosf(f), s = sinf(f);

    int base = (b * NN + n) * 1536 + h * 64;
    int ob   = ((b * HH + h) * NN + n) * 64 + 2 * i;

    float q1 = g_qkv[base + 2*i], q2 = g_qkv[base + 2*i + 1];
    g_q[ob]     = q1 * c - q2 * s;
    g_q[ob + 1] = q1 * s + q2 * c;

    float k1 = g_qkv[base + 512 + 2*i], k2 = g_qkv[base + 512 + 2*i + 1];
    g_k[ob]     = k1 * c - k2 * s;
    g_k[ob + 1] = k1 * s + k2 * c;

    g_v[ob]     = g_qkv[base + 1024 + 2*i];
    g_v[ob + 1] = g_qkv[base + 1024 + 2*i + 1];
}

// --------------------------------------------------------- flash attention -
// One block: 64 queries of one (b,h).  Online softmax over 2048 keys in
// 64-key tiles.  smem: Qs/Ks dim-major [64d][68], Vs [64k][68], Ps [64q][68].
#define APAD 68
#define ASMEM (4 * 64 * APAD * 4)

__global__ __launch_bounds__(256) void attn_kernel()
{
    const int bh = blockIdx.y;            // 0..31
    const int q0 = blockIdx.x * 64;
    const float* __restrict__ Qg = g_q + (size_t)bh * NN * HDIM;
    const float* __restrict__ Kg = g_k + (size_t)bh * NN * HDIM;
    const float* __restrict__ Vg = g_v + (size_t)bh * NN * HDIM;

    extern __shared__ float sm[];
    float* Qs = sm;
    float* Ks = sm + 64 * APAD;
    float* Vs = sm + 2 * 64 * APAD;
    float* Ps = sm + 3 * 64 * APAD;

    const int tid = threadIdx.x;
    const int tx = tid & 15, ty = tid >> 4;
    const int ln  = tid >> 2;             // 0..63 (row of tile)
    const int ld0 = (tid & 3) * 16;       // 0,16,32,48 (dim chunk)

    // Load Q tile transposed (dim-major), pre-scaled by 1/sqrt(hd)
    #pragma unroll
    for (int c = 0; c < 4; c++) {
        float4 v = *(const float4*)&Qg[(q0 + ln) * 64 + ld0 + c * 4];
        Qs[(ld0 + c*4 + 0) * APAD + ln] = v.x * 0.125f;
        Qs[(ld0 + c*4 + 1) * APAD + ln] = v.y * 0.125f;
        Qs[(ld0 + c*4 + 2) * APAD + ln] = v.z * 0.125f;
        Qs[(ld0 + c*4 + 3) * APAD + ln] = v.w * 0.125f;
    }

    float m_i[4], l_i[4], o[4][4];
    #pragma unroll
    for (int i = 0; i < 4; i++) {
        m_i[i] = -1e30f; l_i[i] = 0.f;
        #pragma unroll
        for (int j = 0; j < 4; j++) o[i][j] = 0.f;
    }

    for (int k0 = 0; k0 < NN; k0 += 64) {
        __syncthreads();   // prior PV done before overwriting K/V
        #pragma unroll
        for (int c = 0; c < 4; c++) {
            float4 kv = *(const float4*)&Kg[(k0 + ln) * 64 + ld0 + c * 4];
            Ks[(ld0 + c*4 + 0) * APAD + ln] = kv.x;
            Ks[(ld0 + c*4 + 1) * APAD + ln] = kv.y;
            Ks[(ld0 + c*4 + 2) * APAD + ln] = kv.z;
            Ks[(ld0 + c*4 + 3) * APAD + ln] = kv.w;
            float4 vv = *(const float4*)&Vg[(k0 + ln) * 64 + ld0 + c * 4];
            *(float4*)&Vs[ln * APAD + ld0 + c * 4] = vv;
        }
        __syncthreads();

        // S = Q K^T  (64x64, 4x4 per thread)
        float s[4][4];
        #pragma unroll
        for (int i = 0; i < 4; i++)
            #pragma unroll
            for (int j = 0; j < 4; j++) s[i][j] = 0.f;
        #pragma unroll 8
        for (int kk = 0; kk < 64; kk++) {
            float4 a = *(const float4*)&Qs[kk * APAD + ty * 4];
            float4 b = *(const float4*)&Ks[kk * APAD + tx * 4];
            float av[4] = {a.x, a.y, a.z, a.w};
            float bv[4] = {b.x, b.y, b.z, b.w};
            #pragma unroll
            for (int i = 0; i < 4; i++)
                #pragma unroll
                for (int j = 0; j < 4; j++)
                    s[i][j] = fmaf(av[i], bv[j], s[i][j]);
        }

        // online softmax update
        #pragma unroll
        for (int i = 0; i < 4; i++) {
            float mt = fmaxf(fmaxf(s[i][0], s[i][1]), fmaxf(s[i][2], s[i][3]));
            #pragma unroll
            for (int off = 8; off >= 1; off >>= 1)
                mt = fmaxf(mt, __shfl_xor_sync(0xffffffffu, mt, off));
            float mn = fmaxf(m_i[i], mt);
            float p0 = __expf(s[i][0] - mn);
            float p1 = __expf(s[i][1] - mn);
            float p2 = __expf(s[i][2] - mn);
            float p3 = __expf(s[i][3] - mn);
            float rs = p0 + p1 + p2 + p3;
            #pragma unroll
            for (int off = 8; off >= 1; off >>= 1)
                rs += __shfl_xor_sync(0xffffffffu, rs, off);
            float corr = __expf(m_i[i] - mn);
            l_i[i] = l_i[i] * corr + rs;
            m_i[i] = mn;
            #pragma unroll
            for (int j = 0; j < 4; j++) o[i][j] *= corr;
            float4 p4 = make_float4(p0, p1, p2, p3);
            *(float4*)&Ps[(ty * 4 + i) * APAD + tx * 4] = p4;
        }
        __syncthreads();

        // O += P @ V
        #pragma unroll 8
        for (int kk = 0; kk < 64; kk++) {
            float4 bv = *(const float4*)&Vs[kk * APAD + tx * 4];
            #pragma unroll
            for (int i = 0; i < 4; i++) {
                float p = Ps[(ty * 4 + i) * APAD + kk];
                o[i][0] = fmaf(p, bv.x, o[i][0]);
                o[i][1] = fmaf(p, bv.y, o[i][1]);
                o[i][2] = fmaf(p, bv.z, o[i][2]);
                o[i][3] = fmaf(p, bv.w, o[i][3]);
            }
        }
    }

    // write out in [B,N,D] layout
    const int b = bh >> 3, h = bh & 7;
    #pragma unroll
    for (int i = 0; i < 4; i++) {
        float inv = 1.f / l_i[i];
        int row = q0 + ty * 4 + i;
        float4 v = make_float4(o[i][0]*inv, o[i][1]*inv, o[i][2]*inv, o[i][3]*inv);
        *(float4*)&g_attn[((size_t)(b * NN + row)) * DD + h * 64 + tx * 4] = v;
    }
}

// ------------------------------------------------- copy x into hcat[:,0:512]
__global__ void copy_x_kernel(const float* __restrict__ x)
{
    int idx = blockIdx.x * blockDim.x + threadIdx.x;   // 8192*128 float4s
    if (idx >= MROWS * 128) return;
    int m = idx >> 7, j = idx & 127;
    ((float4*)g_hcat)[m * 256 + j] = ((const float4*)x)[idx];
}

// ------------------------------------------------------- LayerNorm + GELU --
__global__ __launch_bounds__(256) void ln_gelu_kernel(
    const float* __restrict__ gamma, const float* __restrict__ beta)
{
    const int r = blockIdx.x;
    const int t = threadIdx.x;
    float4 v = *(const float4*)&g_h1[(size_t)r * 1024 + t * 4];

    float sum = v.x + v.y + v.z + v.w;
    float sq  = v.x*v.x + v.y*v.y + v.z*v.z + v.w*v.w;
    #pragma unroll
    for (int off = 16; off >= 1; off >>= 1) {
        sum += __shfl_xor_sync(0xffffffffu, sum, off);
        sq  += __shfl_xor_sync(0xffffffffu, sq, off);
    }
    __shared__ float ssum[8], ssq[8];
    if ((t & 31) == 0) { ssum[t >> 5] = sum; ssq[t >> 5] = sq; }
    __syncthreads();
    float tot = 0.f, totq = 0.f;
    #pragma unroll
    for (int w = 0; w < 8; w++) { tot += ssum[w]; totq += ssq[w]; }

    float mean = tot * (1.f / 1024.f);
    float var  = totq * (1.f / 1024.f) - mean * mean;
    float inv  = rsqrtf(var + 1e-5f);

    float4 g4 = *(const float4*)&gamma[t * 4];
    float4 b4 = *(const float4*)&beta[t * 4];
    float y, z; float4 o;
    y = (v.x - mean) * inv * g4.x + b4.x; z = 0.5f * y * (1.f + erff(y * 0.70710678f)); o.x = z;
    y = (v.y - mean) * inv * g4.y + b4.y; z = 0.5f * y * (1.f + erff(y * 0.70710678f)); o.y = z;
    y = (v.z - mean) * inv * g4.z + b4.z; z = 0.5f * y * (1.f + erff(y * 0.70710678f)); o.z = z;
    y = (v.w - mean) * inv * g4.w + b4.w; z = 0.5f * y * (1.f + erff(y * 0.70710678f)); o.w = z;
    *(float4*)&g_h1[(size_t)r * 1024 + t * 4] = o;
}

// ------------------------------------------------------------- launcher ----
extern "C" void kernel_launch(void* const* d_in, const int* in_sizes, int n_in,
                              void* d_out, int out_size)
{
    const float* x      = (const float*)d_in[0];
    const float* freqs  = (const float*)d_in[1];
    const float* wqkv_w = (const float*)d_in[2];
    const float* wqkv_b = (const float*)d_in[3];
    const float* out_w  = (const float*)d_in[4];
    const float* out_b  = (const float*)d_in[5];
    const float* ffn1_w = (const float*)d_in[6];
    const float* ffn1_b = (const float*)d_in[7];
    const float* ln_g   = (const float*)d_in[8];
    const float* ln_b   = (const float*)d_in[9];
    const float* ffn2_w = (const float*)d_in[10];
    const float* ffn2_b = (const float*)d_in[11];
    float* out = (float*)d_out;

    float *p_qkv, *p_attn, *p_hcat, *p_h1;
    cudaGetSymbolAddress((void**)&p_qkv,  g_qkv);
    cudaGetSymbolAddress((void**)&p_attn, g_attn);
    cudaGetSymbolAddress((void**)&p_hcat, g_hcat);
    cudaGetSymbolAddress((void**)&p_h1,   g_h1);

    cudaFuncSetAttribute(attn_kernel,
                         cudaFuncAttributeMaxDynamicSharedMemorySize, ASMEM);

    // 1. QKV projection: [8192,512] @ [512,1536]
    sgemm128<<<dim3(1536/128, MROWS/128), 256>>>(
        x, DD, wqkv_w, 1536, p_qkv, 1536, wqkv_b, nullptr, 0, DD);

    // 2. RoPE + head split
    rope_kernel<<<(BB*NN*HH*32 + 255)/256, 256>>>(freqs);

    // 3. Attention (flash-style, fp32)
    attn_kernel<<<dim3(NN/64, BB*HH), 256, ASMEM>>>();

    // 4. hcat left half = x
    copy_x_kernel<<<(MROWS*128 + 255)/256, 256>>>(x);

    // 5. out-proj into hcat right half: [8192,512]@[512,512]
    sgemm128<<<dim3(512/128, MROWS/128), 256>>>(
        p_attn, DD, out_w, DD, p_hcat + 512, 1024, out_b, nullptr, 0, DD);

    // 6. FFN1: [8192,1024]@[1024,1024]
    sgemm128<<<dim3(1024/128, MROWS/128), 256>>>(
        p_hcat, 1024, ffn1_w, 1024, p_h1, 1024, ffn1_b, nullptr, 0, 1024);

    // 7. LayerNorm + exact GELU (in place on g_h1)
    ln_gelu_kernel<<<MROWS, 256>>>(ln_g, ln_b);

    // 8. FFN2 + residual: out = x + h1 @ [1024,512] + b
    sgemm128<<<dim3(512/128, MROWS/128), 256>>>(
        p_h1, 1024, ffn2_w, DD, out, DD, ffn2_b, x, DD, 1024);
}

// round 2
// speedup vs baseline: 1.4372x; 1.4372x over previous
#include <cuda_runtime.h>
#include <cuda_bf16.h>
#include <math.h>
#include <stdint.h>

// Problem constants
#define BB 4
#define NN 2048
#define DD 512
#define HH 8
#define HDIM 64
#define MROWS (BB*NN)          // 8192

// ---------------- scratch (static device globals; no runtime allocation) ---
__device__ float g_qkv[MROWS*1536];
__device__ float g_q[MROWS*DD];
__device__ float g_k[MROWS*DD];
__device__ float g_v[MROWS*DD];
__device__ float g_attn[MROWS*DD];
__device__ float g_hcat[MROWS*1024];
__device__ float g_h1[MROWS*1024];

// ------------------------------------------------------------ tf32 GEMM ----
// C[M,N] = A[M,K] @ B[K,N] + bias (+ res), via mma.sync.m16n8k8 tf32.
// 128x128x16 CTA tile, 8 warps, 64x32 warp tile (4x4 mma tiles of 16x8).
#define GBM 128
#define GBN 128
#define GBK 16
#define APADW 20    // words per A row in smem  (conflict-free frag loads)
#define BPADW 136   // words per B row in smem  (stride%32==8 -> conflict-free)

__device__ __forceinline__ uint32_t f2tf32(float x) {
    uint32_t u;
    asm volatile("cvt.rna.tf32.f32 %0, %1;" : "=r"(u) : "f"(x));
    return u;
}

__device__ __forceinline__ void mma_tf32(float c[4],
                                         const uint32_t a[4],
                                         const uint32_t b[2]) {
    asm volatile(
        "mma.sync.aligned.m16n8k8.row.col.f32.tf32.tf32.f32 "
        "{%0,%1,%2,%3}, {%4,%5,%6,%7}, {%8,%9}, {%0,%1,%2,%3};\n"
        : "+f"(c[0]), "+f"(c[1]), "+f"(c[2]), "+f"(c[3])
        : "r"(a[0]), "r"(a[1]), "r"(a[2]), "r"(a[3]),
          "r"(b[0]), "r"(b[1]));
}

__global__ __launch_bounds__(256) void gemm_tf32(
    const float* __restrict__ A, int lda,
    const float* __restrict__ Bm, int ldb,
    float* __restrict__ C, int ldc,
    const float* __restrict__ bias,
    const float* __restrict__ res, int ldres,
    int K)
{
    __shared__ uint32_t As[GBM * APADW];   // [m][k], tf32 bits
    __shared__ uint32_t Bs[GBK * BPADW];   // [k][n], tf32 bits

    const int tid  = threadIdx.x;
    const int brow = blockIdx.y * GBM;
    const int bcol = blockIdx.x * GBN;
    const int w    = tid >> 5;
    const int lane = tid & 31;
    const int g    = lane >> 2;
    const int tg   = lane & 3;
    const int wm   = (w & 1) * 64;
    const int wn   = (w >> 1) * 32;

    float acc[4][4][4];
    #pragma unroll
    for (int mi = 0; mi < 4; mi++)
        #pragma unroll
        for (int ni = 0; ni < 4; ni++)
            #pragma unroll
            for (int q = 0; q < 4; q++) acc[mi][ni][q] = 0.f;

    for (int k0 = 0; k0 < K; k0 += GBK) {
        // ---- load A tile 128x16 (row-major -> [m][k] smem, tf32) ----
        #pragma unroll
        for (int it = 0; it < 2; it++) {
            int idx = tid + it * 256;          // 0..511
            int row = idx >> 2;                // 0..127
            int kc  = (idx & 3) * 4;           // 0,4,8,12
            float4 v = *(const float4*)&A[(size_t)(brow + row) * lda + k0 + kc];
            uint4 u;
            u.x = f2tf32(v.x); u.y = f2tf32(v.y);
            u.z = f2tf32(v.z); u.w = f2tf32(v.w);
            *(uint4*)&As[row * APADW + kc] = u;
        }
        // ---- load B tile 16x128 ([k][n] smem, tf32) ----
        #pragma unroll
        for (int it = 0; it < 2; it++) {
            int idx = tid + it * 256;          // 0..511
            int kr  = idx >> 5;                // 0..15
            int nc  = (idx & 31) * 4;          // 0..124
            float4 v = *(const float4*)&Bm[(size_t)(k0 + kr) * ldb + bcol + nc];
            uint4 u;
            u.x = f2tf32(v.x); u.y = f2tf32(v.y);
            u.z = f2tf32(v.z); u.w = f2tf32(v.w);
            *(uint4*)&Bs[kr * BPADW + nc] = u;
        }
        __syncthreads();

        #pragma unroll
        for (int ks = 0; ks < 2; ks++) {
            const int kk = ks * 8;
            uint32_t af[4][4], bf[4][2];
            #pragma unroll
            for (int mi = 0; mi < 4; mi++) {
                int r = wm + mi * 16 + g;
                af[mi][0] = As[r * APADW + kk + tg];
                af[mi][1] = As[(r + 8) * APADW + kk + tg];
                af[mi][2] = As[r * APADW + kk + tg + 4];
                af[mi][3] = As[(r + 8) * APADW + kk + tg + 4];
            }
            #pragma unroll
            for (int ni = 0; ni < 4; ni++) {
                int cc = wn + ni * 8 + g;
                bf[ni][0] = Bs[(kk + tg) * BPADW + cc];
                bf[ni][1] = Bs[(kk + tg + 4) * BPADW + cc];
            }
            #pragma unroll
            for (int mi = 0; mi < 4; mi++)
                #pragma unroll
                for (int ni = 0; ni < 4; ni++)
                    mma_tf32(acc[mi][ni], af[mi], bf[ni]);
        }
        __syncthreads();
    }

    // ---- epilogue: bias (+res) + store ----
    #pragma unroll
    for (int mi = 0; mi < 4; mi++) {
        int r0 = brow + wm + mi * 16 + g;
        int r1 = r0 + 8;
        #pragma unroll
        for (int ni = 0; ni < 4; ni++) {
            int cc = bcol + wn + ni * 8 + tg * 2;
            float2 b2 = *(const float2*)&bias[cc];
            float v0 = acc[mi][ni][0] + b2.x;
            float v1 = acc[mi][ni][1] + b2.y;
            float v2 = acc[mi][ni][2] + b2.x;
            float v3 = acc[mi][ni][3] + b2.y;
            if (res) {
                float2 ra = *(const float2*)&res[(size_t)r0 * ldres + cc];
                float2 rb = *(const float2*)&res[(size_t)r1 * ldres + cc];
                v0 += ra.x; v1 += ra.y; v2 += rb.x; v3 += rb.y;
            }
            *(float2*)&C[(size_t)r0 * ldc + cc] = make_float2(v0, v1);
            *(float2*)&C[(size_t)r1 * ldc + cc] = make_float2(v2, v3);
        }
    }
}

// ------------------------------------------------------------ RoPE split ---
__global__ void rope_kernel(const float* __restrict__ freqs)
{
    int idx = blockIdx.x * blockDim.x + threadIdx.x;
    if (idx >= BB * NN * HH * 32) return;
    int i = idx & 31;
    int h = (idx >> 5) & 7;
    int n = (idx >> 8) & 2047;
    int b = idx >> 19;

    float f = freqs[(b * NN + n) * 32 + i];
    float c = cosf(f), s = sinf(f);

    int base = (b * NN + n) * 1536 + h * 64;
    int ob   = ((b * HH + h) * NN + n) * 64 + 2 * i;

    float q1 = g_qkv[base + 2*i], q2 = g_qkv[base + 2*i + 1];
    g_q[ob]     = q1 * c - q2 * s;
    g_q[ob + 1] = q1 * s + q2 * c;

    float k1 = g_qkv[base + 512 + 2*i], k2 = g_qkv[base + 512 + 2*i + 1];
    g_k[ob]     = k1 * c - k2 * s;
    g_k[ob + 1] = k1 * s + k2 * c;

    g_v[ob]     = g_qkv[base + 1024 + 2*i];
    g_v[ob + 1] = g_qkv[base + 1024 + 2*i + 1];
}

// --------------------------------------------------------- flash attention -
#define APAD 68
#define ASMEM (4 * 64 * APAD * 4)

__global__ __launch_bounds__(256) void attn_kernel()
{
    const int bh = blockIdx.y;
    const int q0 = blockIdx.x * 64;
    const float* __restrict__ Qg = g_q + (size_t)bh * NN * HDIM;
    const float* __restrict__ Kg = g_k + (size_t)bh * NN * HDIM;
    const float* __restrict__ Vg = g_v + (size_t)bh * NN * HDIM;

    extern __shared__ float sm[];
    float* Qs = sm;
    float* Ks = sm + 64 * APAD;
    float* Vs = sm + 2 * 64 * APAD;
    float* Ps = sm + 3 * 64 * APAD;

    const int tid = threadIdx.x;
    const int tx = tid & 15, ty = tid >> 4;
    const int ln  = tid >> 2;
    const int ld0 = (tid & 3) * 16;

    #pragma unroll
    for (int c = 0; c < 4; c++) {
        float4 v = *(const float4*)&Qg[(q0 + ln) * 64 + ld0 + c * 4];
        Qs[(ld0 + c*4 + 0) * APAD + ln] = v.x * 0.125f;
        Qs[(ld0 + c*4 + 1) * APAD + ln] = v.y * 0.125f;
        Qs[(ld0 + c*4 + 2) * APAD + ln] = v.z * 0.125f;
        Qs[(ld0 + c*4 + 3) * APAD + ln] = v.w * 0.125f;
    }

    float m_i[4], l_i[4], o[4][4];
    #pragma unroll
    for (int i = 0; i < 4; i++) {
        m_i[i] = -1e30f; l_i[i] = 0.f;
        #pragma unroll
        for (int j = 0; j < 4; j++) o[i][j] = 0.f;
    }

    for (int k0 = 0; k0 < NN; k0 += 64) {
        __syncthreads();
        #pragma unroll
        for (int c = 0; c < 4; c++) {
            float4 kv = *(const float4*)&Kg[(k0 + ln) * 64 + ld0 + c * 4];
            Ks[(ld0 + c*4 + 0) * APAD + ln] = kv.x;
            Ks[(ld0 + c*4 + 1) * APAD + ln] = kv.y;
            Ks[(ld0 + c*4 + 2) * APAD + ln] = kv.z;
            Ks[(ld0 + c*4 + 3) * APAD + ln] = kv.w;
            float4 vv = *(const float4*)&Vg[(k0 + ln) * 64 + ld0 + c * 4];
            *(float4*)&Vs[ln * APAD + ld0 + c * 4] = vv;
        }
        __syncthreads();

        float s[4][4];
        #pragma unroll
        for (int i = 0; i < 4; i++)
            #pragma unroll
            for (int j = 0; j < 4; j++) s[i][j] = 0.f;
        #pragma unroll 8
        for (int kk = 0; kk < 64; kk++) {
            float4 a = *(const float4*)&Qs[kk * APAD + ty * 4];
            float4 b = *(const float4*)&Ks[kk * APAD + tx * 4];
            float av[4] = {a.x, a.y, a.z, a.w};
            float bv[4] = {b.x, b.y, b.z, b.w};
            #pragma unroll
            for (int i = 0; i < 4; i++)
                #pragma unroll
                for (int j = 0; j < 4; j++)
                    s[i][j] = fmaf(av[i], bv[j], s[i][j]);
        }

        #pragma unroll
        for (int i = 0; i < 4; i++) {
            float mt = fmaxf(fmaxf(s[i][0], s[i][1]), fmaxf(s[i][2], s[i][3]));
            #pragma unroll
            for (int off = 8; off >= 1; off >>= 1)
                mt = fmaxf(mt, __shfl_xor_sync(0xffffffffu, mt, off));
            float mn = fmaxf(m_i[i], mt);
            float p0 = __expf(s[i][0] - mn);
            float p1 = __expf(s[i][1] - mn);
            float p2 = __expf(s[i][2] - mn);
            float p3 = __expf(s[i][3] - mn);
            float rs = p0 + p1 + p2 + p3;
            #pragma unroll
            for (int off = 8; off >= 1; off >>= 1)
                rs += __shfl_xor_sync(0xffffffffu, rs, off);
            float corr = __expf(m_i[i] - mn);
            l_i[i] = l_i[i] * corr + rs;
            m_i[i] = mn;
            #pragma unroll
            for (int j = 0; j < 4; j++) o[i][j] *= corr;
            float4 p4 = make_float4(p0, p1, p2, p3);
            *(float4*)&Ps[(ty * 4 + i) * APAD + tx * 4] = p4;
        }
        __syncthreads();

        #pragma unroll 8
        for (int kk = 0; kk < 64; kk++) {
            float4 bv = *(const float4*)&Vs[kk * APAD + tx * 4];
            #pragma unroll
            for (int i = 0; i < 4; i++) {
                float p = Ps[(ty * 4 + i) * APAD + kk];
                o[i][0] = fmaf(p, bv.x, o[i][0]);
                o[i][1] = fmaf(p, bv.y, o[i][1]);
                o[i][2] = fmaf(p, bv.z, o[i][2]);
                o[i][3] = fmaf(p, bv.w, o[i][3]);
            }
        }
    }

    const int b = bh >> 3, h = bh & 7;
    #pragma unroll
    for (int i = 0; i < 4; i++) {
        float inv = 1.f / l_i[i];
        int row = q0 + ty * 4 + i;
        float4 v = make_float4(o[i][0]*inv, o[i][1]*inv, o[i][2]*inv, o[i][3]*inv);
        *(float4*)&g_attn[((size_t)(b * NN + row)) * DD + h * 64 + tx * 4] = v;
    }
}

// ------------------------------------------------- copy x into hcat[:,0:512]
__global__ void copy_x_kernel(const float* __restrict__ x)
{
    int idx = blockIdx.x * blockDim.x + threadIdx.x;
    if (idx >= MROWS * 128) return;
    int m = idx >> 7, j = idx & 127;
    ((float4*)g_hcat)[m * 256 + j] = ((const float4*)x)[idx];
}

// ------------------------------------------------------- LayerNorm + GELU --
__global__ __launch_bounds__(256) void ln_gelu_kernel(
    const float* __restrict__ gamma, const float* __restrict__ beta)
{
    const int r = blockIdx.x;
    const int t = threadIdx.x;
    float4 v = *(const float4*)&g_h1[(size_t)r * 1024 + t * 4];

    float sum = v.x + v.y + v.z + v.w;
    float sq  = v.x*v.x + v.y*v.y + v.z*v.z + v.w*v.w;
    #pragma unroll
    for (int off = 16; off >= 1; off >>= 1) {
        sum += __shfl_xor_sync(0xffffffffu, sum, off);
        sq  += __shfl_xor_sync(0xffffffffu, sq, off);
    }
    __shared__ float ssum[8], ssq[8];
    if ((t & 31) == 0) { ssum[t >> 5] = sum; ssq[t >> 5] = sq; }
    __syncthreads();
    float tot = 0.f, totq = 0.f;
    #pragma unroll
    for (int w = 0; w < 8; w++) { tot += ssum[w]; totq += ssq[w]; }

    float mean = tot * (1.f / 1024.f);
    float var  = totq * (1.f / 1024.f) - mean * mean;
    float inv  = rsqrtf(var + 1e-5f);

    float4 g4 = *(const float4*)&gamma[t * 4];
    float4 b4 = *(const float4*)&beta[t * 4];
    float y, z; float4 o;
    y = (v.x - mean) * inv * g4.x + b4.x; z = 0.5f * y * (1.f + erff(y * 0.70710678f)); o.x = z;
    y = (v.y - mean) * inv * g4.y + b4.y; z = 0.5f * y * (1.f + erff(y * 0.70710678f)); o.y = z;
    y = (v.z - mean) * inv * g4.z + b4.z; z = 0.5f * y * (1.f + erff(y * 0.70710678f)); o.z = z;
    y = (v.w - mean) * inv * g4.w + b4.w; z = 0.5f * y * (1.f + erff(y * 0.70710678f)); o.w = z;
    *(float4*)&g_h1[(size_t)r * 1024 + t * 4] = o;
}

// ------------------------------------------------------------- launcher ----
extern "C" void kernel_launch(void* const* d_in, const int* in_sizes, int n_in,
                              void* d_out, int out_size)
{
    const float* x      = (const float*)d_in[0];
    const float* freqs  = (const float*)d_in[1];
    const float* wqkv_w = (const float*)d_in[2];
    const float* wqkv_b = (const float*)d_in[3];
    const float* out_w  = (const float*)d_in[4];
    const float* out_b  = (const float*)d_in[5];
    const float* ffn1_w = (const float*)d_in[6];
    const float* ffn1_b = (const float*)d_in[7];
    const float* ln_g   = (const float*)d_in[8];
    const float* ln_b   = (const float*)d_in[9];
    const float* ffn2_w = (const float*)d_in[10];
    const float* ffn2_b = (const float*)d_in[11];
    float* out = (float*)d_out;

    float *p_qkv, *p_attn, *p_hcat, *p_h1;
    cudaGetSymbolAddress((void**)&p_qkv,  g_qkv);
    cudaGetSymbolAddress((void**)&p_attn, g_attn);
    cudaGetSymbolAddress((void**)&p_hcat, g_hcat);
    cudaGetSymbolAddress((void**)&p_h1,   g_h1);

    cudaFuncSetAttribute(attn_kernel,
                         cudaFuncAttributeMaxDynamicSharedMemorySize, ASMEM);

    // 1. QKV projection: [8192,512] @ [512,1536]
    gemm_tf32<<<dim3(1536/GBN, MROWS/GBM), 256>>>(
        x, DD, wqkv_w, 1536, p_qkv, 1536, wqkv_b, nullptr, 0, DD);

    // 2. RoPE + head split
    rope_kernel<<<(BB*NN*HH*32 + 255)/256, 256>>>(freqs);

    // 3. Attention (flash-style, fp32)
    attn_kernel<<<dim3(NN/64, BB*HH), 256, ASMEM>>>();

    // 4. hcat left half = x
    copy_x_kernel<<<(MROWS*128 + 255)/256, 256>>>(x);

    // 5. out-proj into hcat right half: [8192,512]@[512,512]
    gemm_tf32<<<dim3(512/GBN, MROWS/GBM), 256>>>(
        p_attn, DD, out_w, DD, p_hcat + 512, 1024, out_b, nullptr, 0, DD);

    // 6. FFN1: [8192,1024]@[1024,1024]
    gemm_tf32<<<dim3(1024/GBN, MROWS/GBM), 256>>>(
        p_hcat, 1024, ffn1_w, 1024, p_h1, 1024, ffn1_b, nullptr, 0, 1024);

    // 7. LayerNorm + exact GELU (in place on g_h1)
    ln_gelu_kernel<<<MROWS, 256>>>(ln_g, ln_b);

    // 8. FFN2 + residual: out = x + h1 @ [1024,512] + b
    gemm_tf32<<<dim3(512/GBN, MROWS/GBM), 256>>>(
        p_h1, 1024, ffn2_w, DD, out, DD, ffn2_b, x, DD, 1024);
}

// round 3
// speedup vs baseline: 2.5371x; 1.7654x over previous
#include <cuda_runtime.h>
#include <cuda_bf16.h>
#include <math.h>
#include <stdint.h>

// Problem constants
#define BB 4
#define NN 2048
#define DD 512
#define HH 8
#define HDIM 64
#define MROWS (BB*NN)          // 8192

// ---------------- scratch (static device globals; no runtime allocation) ---
__device__ float g_qkv[MROWS*1536];
__device__ float g_q[MROWS*DD];
__device__ float g_k[MROWS*DD];
__device__ float g_v[MROWS*DD];
__device__ float g_attn[MROWS*DD];
__device__ float g_hcat[MROWS*1024];
__device__ float g_h1[MROWS*1024];

// ------------------------------------------------------------ tf32 utils ---
__device__ __forceinline__ uint32_t f2tf32(float x) {
    uint32_t u;
    asm volatile("cvt.rna.tf32.f32 %0, %1;" : "=r"(u) : "f"(x));
    return u;
}

__device__ __forceinline__ void mma_tf32(float c[4],
                                         const uint32_t a[4],
                                         const uint32_t b[2]) {
    asm volatile(
        "mma.sync.aligned.m16n8k8.row.col.f32.tf32.tf32.f32 "
        "{%0,%1,%2,%3}, {%4,%5,%6,%7}, {%8,%9}, {%0,%1,%2,%3};\n"
        : "+f"(c[0]), "+f"(c[1]), "+f"(c[2]), "+f"(c[3])
        : "r"(a[0]), "r"(a[1]), "r"(a[2]), "r"(a[3]),
          "r"(b[0]), "r"(b[1]));
}

// ------------------------------------------------------------ tf32 GEMM ----
#define GBM 128
#define GBN 128
#define GBK 16
#define APADW 20
#define BPADW 136

__global__ __launch_bounds__(256) void gemm_tf32(
    const float* __restrict__ A, int lda,
    const float* __restrict__ Bm, int ldb,
    float* __restrict__ C, int ldc,
    const float* __restrict__ bias,
    const float* __restrict__ res, int ldres,
    int K)
{
    __shared__ uint32_t As[GBM * APADW];
    __shared__ uint32_t Bs[GBK * BPADW];

    const int tid  = threadIdx.x;
    const int brow = blockIdx.y * GBM;
    const int bcol = blockIdx.x * GBN;
    const int w    = tid >> 5;
    const int lane = tid & 31;
    const int g    = lane >> 2;
    const int tg   = lane & 3;
    const int wm   = (w & 1) * 64;
    const int wn   = (w >> 1) * 32;

    float acc[4][4][4];
    #pragma unroll
    for (int mi = 0; mi < 4; mi++)
        #pragma unroll
        for (int ni = 0; ni < 4; ni++)
            #pragma unroll
            for (int q = 0; q < 4; q++) acc[mi][ni][q] = 0.f;

    for (int k0 = 0; k0 < K; k0 += GBK) {
        #pragma unroll
        for (int it = 0; it < 2; it++) {
            int idx = tid + it * 256;
            int row = idx >> 2;
            int kc  = (idx & 3) * 4;
            float4 v = *(const float4*)&A[(size_t)(brow + row) * lda + k0 + kc];
            uint4 u;
            u.x = f2tf32(v.x); u.y = f2tf32(v.y);
            u.z = f2tf32(v.z); u.w = f2tf32(v.w);
            *(uint4*)&As[row * APADW + kc] = u;
        }
        #pragma unroll
        for (int it = 0; it < 2; it++) {
            int idx = tid + it * 256;
            int kr  = idx >> 5;
            int nc  = (idx & 31) * 4;
            float4 v = *(const float4*)&Bm[(size_t)(k0 + kr) * ldb + bcol + nc];
            uint4 u;
            u.x = f2tf32(v.x); u.y = f2tf32(v.y);
            u.z = f2tf32(v.z); u.w = f2tf32(v.w);
            *(uint4*)&Bs[kr * BPADW + nc] = u;
        }
        __syncthreads();

        #pragma unroll
        for (int ks = 0; ks < 2; ks++) {
            const int kk = ks * 8;
            uint32_t af[4][4], bf[4][2];
            #pragma unroll
            for (int mi = 0; mi < 4; mi++) {
                int r = wm + mi * 16 + g;
                af[mi][0] = As[r * APADW + kk + tg];
                af[mi][1] = As[(r + 8) * APADW + kk + tg];
                af[mi][2] = As[r * APADW + kk + tg + 4];
                af[mi][3] = As[(r + 8) * APADW + kk + tg + 4];
            }
            #pragma unroll
            for (int ni = 0; ni < 4; ni++) {
                int cc = wn + ni * 8 + g;
                bf[ni][0] = Bs[(kk + tg) * BPADW + cc];
                bf[ni][1] = Bs[(kk + tg + 4) * BPADW + cc];
            }
            #pragma unroll
            for (int mi = 0; mi < 4; mi++)
                #pragma unroll
                for (int ni = 0; ni < 4; ni++)
                    mma_tf32(acc[mi][ni], af[mi], bf[ni]);
        }
        __syncthreads();
    }

    #pragma unroll
    for (int mi = 0; mi < 4; mi++) {
        int r0 = brow + wm + mi * 16 + g;
        int r1 = r0 + 8;
        #pragma unroll
        for (int ni = 0; ni < 4; ni++) {
            int cc = bcol + wn + ni * 8 + tg * 2;
            float2 b2 = *(const float2*)&bias[cc];
            float v0 = acc[mi][ni][0] + b2.x;
            float v1 = acc[mi][ni][1] + b2.y;
            float v2 = acc[mi][ni][2] + b2.x;
            float v3 = acc[mi][ni][3] + b2.y;
            if (res) {
                float2 ra = *(const float2*)&res[(size_t)r0 * ldres + cc];
                float2 rb = *(const float2*)&res[(size_t)r1 * ldres + cc];
                v0 += ra.x; v1 += ra.y; v2 += rb.x; v3 += rb.y;
            }
            *(float2*)&C[(size_t)r0 * ldc + cc] = make_float2(v0, v1);
            *(float2*)&C[(size_t)r1 * ldc + cc] = make_float2(v2, v3);
        }
    }
}

// ------------------------------------------------------------ RoPE split ---
__global__ void rope_kernel(const float* __restrict__ freqs)
{
    int idx = blockIdx.x * blockDim.x + threadIdx.x;
    if (idx >= BB * NN * HH * 32) return;
    int i = idx & 31;
    int h = (idx >> 5) & 7;
    int n = (idx >> 8) & 2047;
    int b = idx >> 19;

    float f = freqs[(b * NN + n) * 32 + i];
    float c = cosf(f), s = sinf(f);

    int base = (b * NN + n) * 1536 + h * 64;
    int ob   = ((b * HH + h) * NN + n) * 64 + 2 * i;

    float q1 = g_qkv[base + 2*i], q2 = g_qkv[base + 2*i + 1];
    g_q[ob]     = q1 * c - q2 * s;
    g_q[ob + 1] = q1 * s + q2 * c;

    float k1 = g_qkv[base + 512 + 2*i], k2 = g_qkv[base + 512 + 2*i + 1];
    g_k[ob]     = k1 * c - k2 * s;
    g_k[ob + 1] = k1 * s + k2 * c;

    g_v[ob]     = g_qkv[base + 1024 + 2*i];
    g_v[ob + 1] = g_qkv[base + 1024 + 2*i + 1];
}

// ---------------------------------------------- tensor-core flash attention
// Block: 128 queries of one (b,h), 8 warps (16 q-rows each), 64-key tiles.
// smem (tf32 bits): Qs[128][68], Ks[64][68], Vst[64][68] (V transposed),
// Ps[128][68] (warp-private rows).
#define AST 68
#define ATT_SMEM ((128 + 64 + 64 + 128) * AST * 4)

__global__ __launch_bounds__(256) void attn_tc()
{
    const int bh = blockIdx.y;
    const int q0 = blockIdx.x * 128;
    const float* __restrict__ Qg = g_q + (size_t)bh * NN * HDIM;
    const float* __restrict__ Kg = g_k + (size_t)bh * NN * HDIM;
    const float* __restrict__ Vg = g_v + (size_t)bh * NN * HDIM;

    extern __shared__ uint32_t smu[];
    uint32_t* Qs  = smu;                       // 128*AST
    uint32_t* Ks  = smu + 128 * AST;           // 64*AST
    uint32_t* Vst = smu + (128 + 64) * AST;    // 64*AST (dim-major)
    uint32_t* Ps  = smu + (128 + 128) * AST;   // 128*AST

    const int tid  = threadIdx.x;
    const int w    = tid >> 5;
    const int lane = tid & 31;
    const int g    = lane >> 2;
    const int tg   = lane & 3;
    const int w16  = w * 16;

    // ---- load Q (scaled by 1/8, tf32) ----
    {
        int r = tid >> 1, cb = (tid & 1) * 32;
        #pragma unroll
        for (int c = 0; c < 8; c++) {
            float4 v = *(const float4*)&Qg[(size_t)(q0 + r) * 64 + cb + c * 4];
            uint4 u;
            u.x = f2tf32(v.x * 0.125f); u.y = f2tf32(v.y * 0.125f);
            u.z = f2tf32(v.z * 0.125f); u.w = f2tf32(v.w * 0.125f);
            *(uint4*)&Qs[r * AST + cb + c * 4] = u;
        }
    }

    float m0 = -1e30f, m1 = -1e30f, l0 = 0.f, l1 = 0.f;
    float oacc[8][4];
    #pragma unroll
    for (int nt = 0; nt < 8; nt++)
        #pragma unroll
        for (int q = 0; q < 4; q++) oacc[nt][q] = 0.f;

    const int kr  = tid >> 2, kcb = (tid & 3) * 16;   // K load mapping
    const int vk  = tid & 63, vd  = (tid >> 6) * 16;  // V transpose mapping

    for (int k0 = 0; k0 < NN; k0 += 64) {
        __syncthreads();   // prev PV complete / Q loaded
        #pragma unroll
        for (int c = 0; c < 4; c++) {
            float4 v = *(const float4*)&Kg[(size_t)(k0 + kr) * 64 + kcb + c * 4];
            uint4 u;
            u.x = f2tf32(v.x); u.y = f2tf32(v.y);
            u.z = f2tf32(v.z); u.w = f2tf32(v.w);
            *(uint4*)&Ks[kr * AST + kcb + c * 4] = u;
        }
        #pragma unroll
        for (int c = 0; c < 4; c++) {
            float4 v = *(const float4*)&Vg[(size_t)(k0 + vk) * 64 + vd + c * 4];
            Vst[(vd + c*4 + 0) * AST + vk] = f2tf32(v.x);
            Vst[(vd + c*4 + 1) * AST + vk] = f2tf32(v.y);
            Vst[(vd + c*4 + 2) * AST + vk] = f2tf32(v.z);
            Vst[(vd + c*4 + 3) * AST + vk] = f2tf32(v.w);
        }
        __syncthreads();

        // ---- S = Q K^T : warp computes rows [w16, w16+16) x 64 cols ----
        float sacc[8][4];
        #pragma unroll
        for (int nt = 0; nt < 8; nt++)
            #pragma unroll
            for (int q = 0; q < 4; q++) sacc[nt][q] = 0.f;

        #pragma unroll
        for (int ks = 0; ks < 8; ks++) {
            const int kk = ks * 8;
            uint32_t a[4];
            a[0] = Qs[(w16 + g) * AST + kk + tg];
            a[1] = Qs[(w16 + g + 8) * AST + kk + tg];
            a[2] = Qs[(w16 + g) * AST + kk + tg + 4];
            a[3] = Qs[(w16 + g + 8) * AST + kk + tg + 4];
            #pragma unroll
            for (int nt = 0; nt < 8; nt++) {
                uint32_t b[2];
                b[0] = Ks[(nt * 8 + g) * AST + kk + tg];
                b[1] = Ks[(nt * 8 + g) * AST + kk + tg + 4];
                mma_tf32(sacc[nt], a, b);
            }
        }

        // ---- online softmax (rows g and g+8 of this warp's 16) ----
        float mt0 = -1e30f, mt1 = -1e30f;
        #pragma unroll
        for (int nt = 0; nt < 8; nt++) {
            mt0 = fmaxf(mt0, fmaxf(sacc[nt][0], sacc[nt][1]));
            mt1 = fmaxf(mt1, fmaxf(sacc[nt][2], sacc[nt][3]));
        }
        mt0 = fmaxf(mt0, __shfl_xor_sync(0xffffffffu, mt0, 1));
        mt0 = fmaxf(mt0, __shfl_xor_sync(0xffffffffu, mt0, 2));
        mt1 = fmaxf(mt1, __shfl_xor_sync(0xffffffffu, mt1, 1));
        mt1 = fmaxf(mt1, __shfl_xor_sync(0xffffffffu, mt1, 2));
        float mn0 = fmaxf(m0, mt0), mn1 = fmaxf(m1, mt1);

        float rs0 = 0.f, rs1 = 0.f;
        #pragma unroll
        for (int nt = 0; nt < 8; nt++) {
            sacc[nt][0] = __expf(sacc[nt][0] - mn0);
            sacc[nt][1] = __expf(sacc[nt][1] - mn0);
            sacc[nt][2] = __expf(sacc[nt][2] - mn1);
            sacc[nt][3] = __expf(sacc[nt][3] - mn1);
            rs0 += sacc[nt][0] + sacc[nt][1];
            rs1 += sacc[nt][2] + sacc[nt][3];
        }
        rs0 += __shfl_xor_sync(0xffffffffu, rs0, 1);
        rs0 += __shfl_xor_sync(0xffffffffu, rs0, 2);
        rs1 += __shfl_xor_sync(0xffffffffu, rs1, 1);
        rs1 += __shfl_xor_sync(0xffffffffu, rs1, 2);

        float c0 = __expf(m0 - mn0), c1 = __expf(m1 - mn1);
        l0 = l0 * c0 + rs0;  l1 = l1 * c1 + rs1;
        m0 = mn0;            m1 = mn1;
        #pragma unroll
        for (int nt = 0; nt < 8; nt++) {
            oacc[nt][0] *= c0; oacc[nt][1] *= c0;
            oacc[nt][2] *= c1; oacc[nt][3] *= c1;
        }

        // ---- P -> smem (warp-private rows; A-fragment layout next) ----
        #pragma unroll
        for (int nt = 0; nt < 8; nt++) {
            uint2 u0, u1;
            u0.x = f2tf32(sacc[nt][0]); u0.y = f2tf32(sacc[nt][1]);
            u1.x = f2tf32(sacc[nt][2]); u1.y = f2tf32(sacc[nt][3]);
            *(uint2*)&Ps[(w16 + g) * AST + nt * 8 + tg * 2]     = u0;
            *(uint2*)&Ps[(w16 + g + 8) * AST + nt * 8 + tg * 2] = u1;
        }
        __syncwarp();

        // ---- O += P @ V ----
        #pragma unroll
        for (int ks = 0; ks < 8; ks++) {
            const int kk = ks * 8;
            uint32_t a[4];
            a[0] = Ps[(w16 + g) * AST + kk + tg];
            a[1] = Ps[(w16 + g + 8) * AST + kk + tg];
            a[2] = Ps[(w16 + g) * AST + kk + tg + 4];
            a[3] = Ps[(w16 + g + 8) * AST + kk + tg + 4];
            #pragma unroll
            for (int nt = 0; nt < 8; nt++) {
                uint32_t b[2];
                b[0] = Vst[(nt * 8 + g) * AST + kk + tg];
                b[1] = Vst[(nt * 8 + g) * AST + kk + tg + 4];
                mma_tf32(oacc[nt], a, b);
            }
        }
    }

    // ---- write out [B,N,D] ----
    const int b = bh >> 3, h = bh & 7;
    const float inv0 = 1.f / l0, inv1 = 1.f / l1;
    const int r0 = q0 + w16 + g, r1 = r0 + 8;
    #pragma unroll
    for (int nt = 0; nt < 8; nt++) {
        int d = h * 64 + nt * 8 + tg * 2;
        *(float2*)&g_attn[(size_t)(b * NN + r0) * DD + d] =
            make_float2(oacc[nt][0] * inv0, oacc[nt][1] * inv0);
        *(float2*)&g_attn[(size_t)(b * NN + r1) * DD + d] =
            make_float2(oacc[nt][2] * inv1, oacc[nt][3] * inv1);
    }
}

// ------------------------------------------------- copy x into hcat[:,0:512]
__global__ void copy_x_kernel(const float* __restrict__ x)
{
    int idx = blockIdx.x * blockDim.x + threadIdx.x;
    if (idx >= MROWS * 128) return;
    int m = idx >> 7, j = idx & 127;
    ((float4*)g_hcat)[m * 256 + j] = ((const float4*)x)[idx];
}

// ------------------------------------------------------- LayerNorm + GELU --
__global__ __launch_bounds__(256) void ln_gelu_kernel(
    const float* __restrict__ gamma, const float* __restrict__ beta)
{
    const int r = blockIdx.x;
    const int t = threadIdx.x;
    float4 v = *(const float4*)&g_h1[(size_t)r * 1024 + t * 4];

    float sum = v.x + v.y + v.z + v.w;
    float sq  = v.x*v.x + v.y*v.y + v.z*v.z + v.w*v.w;
    #pragma unroll
    for (int off = 16; off >= 1; off >>= 1) {
        sum += __shfl_xor_sync(0xffffffffu, sum, off);
        sq  += __shfl_xor_sync(0xffffffffu, sq, off);
    }
    __shared__ float ssum[8], ssq[8];
    if ((t & 31) == 0) { ssum[t >> 5] = sum; ssq[t >> 5] = sq; }
    __syncthreads();
    float tot = 0.f, totq = 0.f;
    #pragma unroll
    for (int w = 0; w < 8; w++) { tot += ssum[w]; totq += ssq[w]; }

    float mean = tot * (1.f / 1024.f);
    float var  = totq * (1.f / 1024.f) - mean * mean;
    float inv  = rsqrtf(var + 1e-5f);

    float4 g4 = *(const float4*)&gamma[t * 4];
    float4 b4 = *(const float4*)&beta[t * 4];
    float y, z; float4 o;
    y = (v.x - mean) * inv * g4.x + b4.x; z = 0.5f * y * (1.f + erff(y * 0.70710678f)); o.x = z;
    y = (v.y - mean) * inv * g4.y + b4.y; z = 0.5f * y * (1.f + erff(y * 0.70710678f)); o.y = z;
    y = (v.z - mean) * inv * g4.z + b4.z; z = 0.5f * y * (1.f + erff(y * 0.70710678f)); o.z = z;
    y = (v.w - mean) * inv * g4.w + b4.w; z = 0.5f * y * (1.f + erff(y * 0.70710678f)); o.w = z;
    *(float4*)&g_h1[(size_t)r * 1024 + t * 4] = o;
}

// ------------------------------------------------------------- launcher ----
extern "C" void kernel_launch(void* const* d_in, const int* in_sizes, int n_in,
                              void* d_out, int out_size)
{
    const float* x      = (const float*)d_in[0];
    const float* freqs  = (const float*)d_in[1];
    const float* wqkv_w = (const float*)d_in[2];
    const float* wqkv_b = (const float*)d_in[3];
    const float* out_w  = (const float*)d_in[4];
    const float* out_b  = (const float*)d_in[5];
    const float* ffn1_w = (const float*)d_in[6];
    const float* ffn1_b = (const float*)d_in[7];
    const float* ln_g   = (const float*)d_in[8];
    const float* ln_b   = (const float*)d_in[9];
    const float* ffn2_w = (const float*)d_in[10];
    const float* ffn2_b = (const float*)d_in[11];
    float* out = (float*)d_out;

    float *p_qkv, *p_attn, *p_hcat, *p_h1;
    cudaGetSymbolAddress((void**)&p_qkv,  g_qkv);
    cudaGetSymbolAddress((void**)&p_attn, g_attn);
    cudaGetSymbolAddress((void**)&p_hcat, g_hcat);
    cudaGetSymbolAddress((void**)&p_h1,   g_h1);

    cudaFuncSetAttribute(attn_tc,
                         cudaFuncAttributeMaxDynamicSharedMemorySize, ATT_SMEM);

    // 1. QKV projection: [8192,512] @ [512,1536]
    gemm_tf32<<<dim3(1536/GBN, MROWS/GBM), 256>>>(
        x, DD, wqkv_w, 1536, p_qkv, 1536, wqkv_b, nullptr, 0, DD);

    // 2. RoPE + head split
    rope_kernel<<<(BB*NN*HH*32 + 255)/256, 256>>>(freqs);

    // 3. Attention (flash-style, tf32 tensor cores)
    attn_tc<<<dim3(NN/128, BB*HH), 256, ATT_SMEM>>>();

    // 4. hcat left half = x
    copy_x_kernel<<<(MROWS*128 + 255)/256, 256>>>(x);

    // 5. out-proj into hcat right half: [8192,512]@[512,512]
    gemm_tf32<<<dim3(512/GBN, MROWS/GBM), 256>>>(
        p_attn, DD, out_w, DD, p_hcat + 512, 1024, out_b, nullptr, 0, DD);

    // 6. FFN1: [8192,1024]@[1024,1024]
    gemm_tf32<<<dim3(1024/GBN, MROWS/GBM), 256>>>(
        p_hcat, 1024, ffn1_w, 1024, p_h1, 1024, ffn1_b, nullptr, 0, 1024);

    // 7. LayerNorm + exact GELU (in place on g_h1)
    ln_gelu_kernel<<<MROWS, 256>>>(ln_g, ln_b);

    // 8. FFN2 + residual: out = x + h1 @ [1024,512] + b
    gemm_tf32<<<dim3(512/GBN, MROWS/GBM), 256>>>(
        p_h1, 1024, ffn2_w, DD, out, DD, ffn2_b, x, DD, 1024);
}

// round 4
// speedup vs baseline: 2.6194x; 1.0324x over previous
#include <cuda_runtime.h>
#include <cuda_bf16.h>
#include <math.h>
#include <stdint.h>

// Problem constants
#define BB 4
#define NN 2048
#define DD 512
#define HH 8
#define HDIM 64
#define MROWS (BB*NN)          // 8192

// ---------------- scratch (static device globals; no runtime allocation) ---
__device__ float g_qkv[MROWS*1536];
__device__ float g_q[MROWS*DD];
__device__ float g_k[MROWS*DD];
__device__ float g_v[MROWS*DD];
__device__ float g_attn[MROWS*DD];
__device__ float g_hcat[MROWS*1024];
__device__ float g_h1[MROWS*1024];
__device__ float g_xr[MROWS*DD];          // tf32-rounded x
__device__ float g_wr[2621440];           // tf32-rounded weights (all 4)

#define WOFF_QKV  0
#define WOFF_OUT  786432
#define WOFF_FFN1 1048576
#define WOFF_FFN2 2097152

// ------------------------------------------------------------ tf32 utils ---
__device__ __forceinline__ uint32_t f2tf32(float x) {
    uint32_t u;
    asm volatile("cvt.rna.tf32.f32 %0, %1;" : "=r"(u) : "f"(x));
    return u;
}
__device__ __forceinline__ float roundtf(float x) {
    return __uint_as_float(f2tf32(x));
}

__device__ __forceinline__ void mma_tf32(float c[4],
                                         const uint32_t a[4],
                                         const uint32_t b[2]) {
    asm volatile(
        "mma.sync.aligned.m16n8k8.row.col.f32.tf32.tf32.f32 "
        "{%0,%1,%2,%3}, {%4,%5,%6,%7}, {%8,%9}, {%0,%1,%2,%3};\n"
        : "+f"(c[0]), "+f"(c[1]), "+f"(c[2]), "+f"(c[3])
        : "r"(a[0]), "r"(a[1]), "r"(a[2]), "r"(a[3]),
          "r"(b[0]), "r"(b[1]));
}

__device__ __forceinline__ void cp_async16(uint32_t saddr, const void* gptr) {
    asm volatile("cp.async.cg.shared.global [%0], [%1], 16;\n"
                 :: "r"(saddr), "l"(gptr));
}
#define CP_COMMIT() asm volatile("cp.async.commit_group;\n" ::: "memory")
#define CP_WAIT1()  asm volatile("cp.async.wait_group 1;\n" ::: "memory")
#define CP_WAIT0()  asm volatile("cp.async.wait_group 0;\n" ::: "memory")

// ------------------------------------------------ pre-round x and weights --
__global__ __launch_bounds__(256) void round_inputs(
    const float* __restrict__ x,
    const float* __restrict__ w_qkv,
    const float* __restrict__ w_out,
    const float* __restrict__ w_ffn1,
    const float* __restrict__ w_ffn2)
{
    int idx = blockIdx.x * blockDim.x + threadIdx.x;  // float4 index
    // segment sizes in float4s
    const int nx = MROWS*DD/4;          // 1048576
    const int n0 = 786432/4;            // 196608
    const int n1 = 262144/4;            // 65536
    const int n2 = 1048576/4;           // 262144
    const int n3 = 524288/4;            // 131072
    const float4* src; float4* dst;
    if (idx < nx)                    { src = (const float4*)x     + idx;        dst = (float4*)g_xr + idx; }
    else if ((idx -= nx) < n0)       { src = (const float4*)w_qkv + idx;        dst = (float4*)(g_wr + WOFF_QKV) + idx; }
    else if ((idx -= n0) < n1)       { src = (const float4*)w_out + idx;        dst = (float4*)(g_wr + WOFF_OUT) + idx; }
    else if ((idx -= n1) < n2)       { src = (const float4*)w_ffn1 + idx;       dst = (float4*)(g_wr + WOFF_FFN1) + idx; }
    else if ((idx -= n2) < n3)       { src = (const float4*)w_ffn2 + idx;       dst = (float4*)(g_wr + WOFF_FFN2) + idx; }
    else return;
    float4 v = *src;
    v.x = roundtf(v.x); v.y = roundtf(v.y);
    v.z = roundtf(v.z); v.w = roundtf(v.w);
    *dst = v;
}

// --------------------------------------------- pipelined tf32 GEMM ---------
// Operands MUST be pre-rounded to tf32 bit patterns (truncation then exact).
#define GBM 128
#define GBN 128
#define GBK 16
#define APADW 20
#define BPADW 136

__global__ __launch_bounds__(256) void gemm_tf32(
    const float* __restrict__ A, int lda,
    const float* __restrict__ Bm, int ldb,
    float* __restrict__ C, int ldc,
    const float* __restrict__ bias,
    const float* __restrict__ res, int ldres,
    int K, int roundC)
{
    __shared__ uint32_t As[2][GBM * APADW];
    __shared__ uint32_t Bs[2][GBK * BPADW];

    const int tid  = threadIdx.x;
    const int brow = blockIdx.y * GBM;
    const int bcol = blockIdx.x * GBN;
    const int w    = tid >> 5;
    const int lane = tid & 31;
    const int g    = lane >> 2;
    const int tg   = lane & 3;
    const int wm   = (w & 1) * 64;
    const int wn   = (w >> 1) * 32;

    // per-thread load coordinates
    const int ar0 = tid >> 2,  ac0 = (tid & 3) * 4;        // A chunk 0
    const int ar1 = ar0 + 64;                              // A chunk 1
    const int bk0 = tid >> 5,  bn0 = (tid & 31) * 4;       // B chunk 0
    const int bk1 = bk0 + 8;                               // B chunk 1

    uint32_t sA0[2], sA1[2], sB0[2], sB1[2];
    #pragma unroll
    for (int s = 0; s < 2; s++) {
        sA0[s] = (uint32_t)__cvta_generic_to_shared(&As[s][ar0 * APADW + ac0]);
        sA1[s] = (uint32_t)__cvta_generic_to_shared(&As[s][ar1 * APADW + ac0]);
        sB0[s] = (uint32_t)__cvta_generic_to_shared(&Bs[s][bk0 * BPADW + bn0]);
        sB1[s] = (uint32_t)__cvta_generic_to_shared(&Bs[s][bk1 * BPADW + bn0]);
    }

    float acc[4][4][4];
    #pragma unroll
    for (int mi = 0; mi < 4; mi++)
        #pragma unroll
        for (int ni = 0; ni < 4; ni++)
            #pragma unroll
            for (int q = 0; q < 4; q++) acc[mi][ni][q] = 0.f;

    const int nk = K / GBK;

    // issue stage 0
    {
        cp_async16(sA0[0], &A[(size_t)(brow + ar0) * lda + ac0]);
        cp_async16(sA1[0], &A[(size_t)(brow + ar1) * lda + ac0]);
        cp_async16(sB0[0], &Bm[(size_t)(bk0) * ldb + bcol + bn0]);
        cp_async16(sB1[0], &Bm[(size_t)(bk1) * ldb + bcol + bn0]);
        CP_COMMIT();
    }

    for (int kt = 0; kt < nk; kt++) {
        const int s = kt & 1;
        if (kt + 1 < nk) {
            const int k0 = (kt + 1) * GBK;
            cp_async16(sA0[s^1], &A[(size_t)(brow + ar0) * lda + k0 + ac0]);
            cp_async16(sA1[s^1], &A[(size_t)(brow + ar1) * lda + k0 + ac0]);
            cp_async16(sB0[s^1], &Bm[(size_t)(k0 + bk0) * ldb + bcol + bn0]);
            cp_async16(sB1[s^1], &Bm[(size_t)(k0 + bk1) * ldb + bcol + bn0]);
            CP_COMMIT();
            CP_WAIT1();
        } else {
            CP_WAIT0();
        }
        __syncthreads();

        #pragma unroll
        for (int ks = 0; ks < 2; ks++) {
            const int kk = ks * 8;
            uint32_t af[4][4], bf[4][2];
            #pragma unroll
            for (int mi = 0; mi < 4; mi++) {
                int r = wm + mi * 16 + g;
                af[mi][0] = As[s][r * APADW + kk + tg];
                af[mi][1] = As[s][(r + 8) * APADW + kk + tg];
                af[mi][2] = As[s][r * APADW + kk + tg + 4];
                af[mi][3] = As[s][(r + 8) * APADW + kk + tg + 4];
            }
            #pragma unroll
            for (int ni = 0; ni < 4; ni++) {
                int cc = wn + ni * 8 + g;
                bf[ni][0] = Bs[s][(kk + tg) * BPADW + cc];
                bf[ni][1] = Bs[s][(kk + tg + 4) * BPADW + cc];
            }
            #pragma unroll
            for (int mi = 0; mi < 4; mi++)
                #pragma unroll
                for (int ni = 0; ni < 4; ni++)
                    mma_tf32(acc[mi][ni], af[mi], bf[ni]);
        }
        __syncthreads();
    }

    #pragma unroll
    for (int mi = 0; mi < 4; mi++) {
        int r0 = brow + wm + mi * 16 + g;
        int r1 = r0 + 8;
        #pragma unroll
        for (int ni = 0; ni < 4; ni++) {
            int cc = bcol + wn + ni * 8 + tg * 2;
            float2 b2 = *(const float2*)&bias[cc];
            float v0 = acc[mi][ni][0] + b2.x;
            float v1 = acc[mi][ni][1] + b2.y;
            float v2 = acc[mi][ni][2] + b2.x;
            float v3 = acc[mi][ni][3] + b2.y;
            if (res) {
                float2 ra = *(const float2*)&res[(size_t)r0 * ldres + cc];
                float2 rb = *(const float2*)&res[(size_t)r1 * ldres + cc];
                v0 += ra.x; v1 += ra.y; v2 += rb.x; v3 += rb.y;
            }
            if (roundC) {
                v0 = roundtf(v0); v1 = roundtf(v1);
                v2 = roundtf(v2); v3 = roundtf(v3);
            }
            *(float2*)&C[(size_t)r0 * ldc + cc] = make_float2(v0, v1);
            *(float2*)&C[(size_t)r1 * ldc + cc] = make_float2(v2, v3);
        }
    }
}

// ------------------------------------------------------------ RoPE split ---
// Writes tf32-rounded q,k,v (they feed tensor-core matmuls downstream).
__global__ void rope_kernel(const float* __restrict__ freqs)
{
    int idx = blockIdx.x * blockDim.x + threadIdx.x;
    if (idx >= BB * NN * HH * 32) return;
    int i = idx & 31;
    int h = (idx >> 5) & 7;
    int n = (idx >> 8) & 2047;
    int b = idx >> 19;

    float f = freqs[(b * NN + n) * 32 + i];
    float c = cosf(f), s = sinf(f);

    int base = (b * NN + n) * 1536 + h * 64;
    int ob   = ((b * HH + h) * NN + n) * 64 + 2 * i;

    float q1 = g_qkv[base + 2*i], q2 = g_qkv[base + 2*i + 1];
    g_q[ob]     = roundtf(q1 * c - q2 * s);
    g_q[ob + 1] = roundtf(q1 * s + q2 * c);

    float k1 = g_qkv[base + 512 + 2*i], k2 = g_qkv[base + 512 + 2*i + 1];
    g_k[ob]     = roundtf(k1 * c - k2 * s);
    g_k[ob + 1] = roundtf(k1 * s + k2 * c);

    g_v[ob]     = roundtf(g_qkv[base + 1024 + 2*i]);
    g_v[ob + 1] = roundtf(g_qkv[base + 1024 + 2*i + 1]);
}

// ---------------------------------------------- tensor-core flash attention
#define AST 68
#define ATT_SMEM ((128 + 64 + 64 + 128) * AST * 4)

__global__ __launch_bounds__(256) void attn_tc()
{
    const int bh = blockIdx.y;
    const int q0 = blockIdx.x * 128;
    const float* __restrict__ Qg = g_q + (size_t)bh * NN * HDIM;
    const float* __restrict__ Kg = g_k + (size_t)bh * NN * HDIM;
    const float* __restrict__ Vg = g_v + (size_t)bh * NN * HDIM;

    extern __shared__ uint32_t smu[];
    uint32_t* Qs  = smu;
    uint32_t* Ks  = smu + 128 * AST;
    uint32_t* Vst = smu + (128 + 64) * AST;
    uint32_t* Ps  = smu + (128 + 128) * AST;

    const int tid  = threadIdx.x;
    const int w    = tid >> 5;
    const int lane = tid & 31;
    const int g    = lane >> 2;
    const int tg   = lane & 3;
    const int w16  = w * 16;

    // ---- load Q (scaled by 1/8 — exact, preserves tf32 rounding) ----
    {
        int r = tid >> 1, cb = (tid & 1) * 32;
        #pragma unroll
        for (int c = 0; c < 8; c++) {
            float4 v = *(const float4*)&Qg[(size_t)(q0 + r) * 64 + cb + c * 4];
            uint4 u;
            u.x = __float_as_uint(v.x * 0.125f);
            u.y = __float_as_uint(v.y * 0.125f);
            u.z = __float_as_uint(v.z * 0.125f);
            u.w = __float_as_uint(v.w * 0.125f);
            *(uint4*)&Qs[r * AST + cb + c * 4] = u;
        }
    }

    float m0 = -1e30f, m1 = -1e30f, l0 = 0.f, l1 = 0.f;
    float oacc[8][4];
    #pragma unroll
    for (int nt = 0; nt < 8; nt++)
        #pragma unroll
        for (int q = 0; q < 4; q++) oacc[nt][q] = 0.f;

    const int kr  = tid >> 2, kcb = (tid & 3) * 16;
    const int vk  = tid & 63, vd  = (tid >> 6) * 16;

    for (int k0 = 0; k0 < NN; k0 += 64) {
        __syncthreads();
        #pragma unroll
        for (int c = 0; c < 4; c++) {
            uint4 u = *(const uint4*)&Kg[(size_t)(k0 + kr) * 64 + kcb + c * 4];
            *(uint4*)&Ks[kr * AST + kcb + c * 4] = u;
        }
        #pragma unroll
        for (int c = 0; c < 4; c++) {
            float4 v = *(const float4*)&Vg[(size_t)(k0 + vk) * 64 + vd + c * 4];
            Vst[(vd + c*4 + 0) * AST + vk] = __float_as_uint(v.x);
            Vst[(vd + c*4 + 1) * AST + vk] = __float_as_uint(v.y);
            Vst[(vd + c*4 + 2) * AST + vk] = __float_as_uint(v.z);
            Vst[(vd + c*4 + 3) * AST + vk] = __float_as_uint(v.w);
        }
        __syncthreads();

        float sacc[8][4];
        #pragma unroll
        for (int nt = 0; nt < 8; nt++)
            #pragma unroll
            for (int q = 0; q < 4; q++) sacc[nt][q] = 0.f;

        #pragma unroll
        for (int ks = 0; ks < 8; ks++) {
            const int kk = ks * 8;
            uint32_t a[4];
            a[0] = Qs[(w16 + g) * AST + kk + tg];
            a[1] = Qs[(w16 + g + 8) * AST + kk + tg];
            a[2] = Qs[(w16 + g) * AST + kk + tg + 4];
            a[3] = Qs[(w16 + g + 8) * AST + kk + tg + 4];
            #pragma unroll
            for (int nt = 0; nt < 8; nt++) {
                uint32_t b[2];
                b[0] = Ks[(nt * 8 + g) * AST + kk + tg];
                b[1] = Ks[(nt * 8 + g) * AST + kk + tg + 4];
                mma_tf32(sacc[nt], a, b);
            }
        }

        float mt0 = -1e30f, mt1 = -1e30f;
        #pragma unroll
        for (int nt = 0; nt < 8; nt++) {
            mt0 = fmaxf(mt0, fmaxf(sacc[nt][0], sacc[nt][1]));
            mt1 = fmaxf(mt1, fmaxf(sacc[nt][2], sacc[nt][3]));
        }
        mt0 = fmaxf(mt0, __shfl_xor_sync(0xffffffffu, mt0, 1));
        mt0 = fmaxf(mt0, __shfl_xor_sync(0xffffffffu, mt0, 2));
        mt1 = fmaxf(mt1, __shfl_xor_sync(0xffffffffu, mt1, 1));
        mt1 = fmaxf(mt1, __shfl_xor_sync(0xffffffffu, mt1, 2));
        float mn0 = fmaxf(m0, mt0), mn1 = fmaxf(m1, mt1);

        float rs0 = 0.f, rs1 = 0.f;
        #pragma unroll
        for (int nt = 0; nt < 8; nt++) {
            sacc[nt][0] = __expf(sacc[nt][0] - mn0);
            sacc[nt][1] = __expf(sacc[nt][1] - mn0);
            sacc[nt][2] = __expf(sacc[nt][2] - mn1);
            sacc[nt][3] = __expf(sacc[nt][3] - mn1);
            rs0 += sacc[nt][0] + sacc[nt][1];
            rs1 += sacc[nt][2] + sacc[nt][3];
        }
        rs0 += __shfl_xor_sync(0xffffffffu, rs0, 1);
        rs0 += __shfl_xor_sync(0xffffffffu, rs0, 2);
        rs1 += __shfl_xor_sync(0xffffffffu, rs1, 1);
        rs1 += __shfl_xor_sync(0xffffffffu, rs1, 2);

        float c0 = __expf(m0 - mn0), c1 = __expf(m1 - mn1);
        l0 = l0 * c0 + rs0;  l1 = l1 * c1 + rs1;
        m0 = mn0;            m1 = mn1;
        #pragma unroll
        for (int nt = 0; nt < 8; nt++) {
            oacc[nt][0] *= c0; oacc[nt][1] *= c0;
            oacc[nt][2] *= c1; oacc[nt][3] *= c1;
        }

        #pragma unroll
        for (int nt = 0; nt < 8; nt++) {
            uint2 u0, u1;
            u0.x = f2tf32(sacc[nt][0]); u0.y = f2tf32(sacc[nt][1]);
            u1.x = f2tf32(sacc[nt][2]); u1.y = f2tf32(sacc[nt][3]);
            *(uint2*)&Ps[(w16 + g) * AST + nt * 8 + tg * 2]     = u0;
            *(uint2*)&Ps[(w16 + g + 8) * AST + nt * 8 + tg * 2] = u1;
        }
        __syncwarp();

        #pragma unroll
        for (int ks = 0; ks < 8; ks++) {
            const int kk = ks * 8;
            uint32_t a[4];
            a[0] = Ps[(w16 + g) * AST + kk + tg];
            a[1] = Ps[(w16 + g + 8) * AST + kk + tg];
            a[2] = Ps[(w16 + g) * AST + kk + tg + 4];
            a[3] = Ps[(w16 + g + 8) * AST + kk + tg + 4];
            #pragma unroll
            for (int nt = 0; nt < 8; nt++) {
                uint32_t b[2];
                b[0] = Vst[(nt * 8 + g) * AST + kk + tg];
                b[1] = Vst[(nt * 8 + g) * AST + kk + tg + 4];
                mma_tf32(oacc[nt], a, b);
            }
        }
    }

    // ---- write out [B,N,D], tf32-rounded (feeds out-proj GEMM A) ----
    const int b = bh >> 3, h = bh & 7;
    const float inv0 = 1.f / l0, inv1 = 1.f / l1;
    const int r0 = q0 + w16 + g, r1 = r0 + 8;
    #pragma unroll
    for (int nt = 0; nt < 8; nt++) {
        int d = h * 64 + nt * 8 + tg * 2;
        *(float2*)&g_attn[(size_t)(b * NN + r0) * DD + d] =
            make_float2(roundtf(oacc[nt][0] * inv0), roundtf(oacc[nt][1] * inv0));
        *(float2*)&g_attn[(size_t)(b * NN + r1) * DD + d] =
            make_float2(roundtf(oacc[nt][2] * inv1), roundtf(oacc[nt][3] * inv1));
    }
}

// ------------------------------------- copy rounded x into hcat[:,0:512] ---
__global__ void copy_x_kernel(const float* __restrict__ x)
{
    int idx = blockIdx.x * blockDim.x + threadIdx.x;
    if (idx >= MROWS * 128) return;
    int m = idx >> 7, j = idx & 127;
    float4 v = ((const float4*)x)[idx];
    v.x = roundtf(v.x); v.y = roundtf(v.y);
    v.z = roundtf(v.z); v.w = roundtf(v.w);
    ((float4*)g_hcat)[m * 256 + j] = v;
}

// ------------------------------------------------------- LayerNorm + GELU --
// Stores tf32-rounded (feeds FFN2 GEMM A).
__global__ __launch_bounds__(256) void ln_gelu_kernel(
    const float* __restrict__ gamma, const float* __restrict__ beta)
{
    const int r = blockIdx.x;
    const int t = threadIdx.x;
    float4 v = *(const float4*)&g_h1[(size_t)r * 1024 + t * 4];

    float sum = v.x + v.y + v.z + v.w;
    float sq  = v.x*v.x + v.y*v.y + v.z*v.z + v.w*v.w;
    #pragma unroll
    for (int off = 16; off >= 1; off >>= 1) {
        sum += __shfl_xor_sync(0xffffffffu, sum, off);
        sq  += __shfl_xor_sync(0xffffffffu, sq, off);
    }
    __shared__ float ssum[8], ssq[8];
    if ((t & 31) == 0) { ssum[t >> 5] = sum; ssq[t >> 5] = sq; }
    __syncthreads();
    float tot = 0.f, totq = 0.f;
    #pragma unroll
    for (int w = 0; w < 8; w++) { tot += ssum[w]; totq += ssq[w]; }

    float mean = tot * (1.f / 1024.f);
    float var  = totq * (1.f / 1024.f) - mean * mean;
    float inv  = rsqrtf(var + 1e-5f);

    float4 g4 = *(const float4*)&gamma[t * 4];
    float4 b4 = *(const float4*)&beta[t * 4];
    float y; float4 o;
    y = (v.x - mean) * inv * g4.x + b4.x; o.x = roundtf(0.5f * y * (1.f + erff(y * 0.70710678f)));
    y = (v.y - mean) * inv * g4.y + b4.y; o.y = roundtf(0.5f * y * (1.f + erff(y * 0.70710678f)));
    y = (v.z - mean) * inv * g4.z + b4.z; o.z = roundtf(0.5f * y * (1.f + erff(y * 0.70710678f)));
    y = (v.w - mean) * inv * g4.w + b4.w; o.w = roundtf(0.5f * y * (1.f + erff(y * 0.70710678f)));
    *(float4*)&g_h1[(size_t)r * 1024 + t * 4] = o;
}

// ------------------------------------------------------------- launcher ----
extern "C" void kernel_launch(void* const* d_in, const int* in_sizes, int n_in,
                              void* d_out, int out_size)
{
    const float* x      = (const float*)d_in[0];
    const float* freqs  = (const float*)d_in[1];
    const float* wqkv_w = (const float*)d_in[2];
    const float* wqkv_b = (const float*)d_in[3];
    const float* out_w  = (const float*)d_in[4];
    const float* out_b  = (const float*)d_in[5];
    const float* ffn1_w = (const float*)d_in[6];
    const float* ffn1_b = (const float*)d_in[7];
    const float* ln_g   = (const float*)d_in[8];
    const float* ln_b   = (const float*)d_in[9];
    const float* ffn2_w = (const float*)d_in[10];
    const float* ffn2_b = (const float*)d_in[11];
    float* out = (float*)d_out;

    float *p_qkv, *p_attn, *p_hcat, *p_h1, *p_xr, *p_wr;
    cudaGetSymbolAddress((void**)&p_qkv,  g_qkv);
    cudaGetSymbolAddress((void**)&p_attn, g_attn);
    cudaGetSymbolAddress((void**)&p_hcat, g_hcat);
    cudaGetSymbolAddress((void**)&p_h1,   g_h1);
    cudaGetSymbolAddress((void**)&p_xr,   g_xr);
    cudaGetSymbolAddress((void**)&p_wr,   g_wr);

    cudaFuncSetAttribute(attn_tc,
                         cudaFuncAttributeMaxDynamicSharedMemorySize, ATT_SMEM);

    // 0. round x + all weights to tf32 bit patterns
    {
        int total_f4 = MROWS*DD/4 + (786432 + 262144 + 1048576 + 524288)/4;
        round_inputs<<<(total_f4 + 255)/256, 256>>>(x, wqkv_w, out_w, ffn1_w, ffn2_w);
    }

    // 1. QKV projection: [8192,512] @ [512,1536]
    gemm_tf32<<<dim3(1536/GBN, MROWS/GBM), 256>>>(
        p_xr, DD, p_wr + WOFF_QKV, 1536, p_qkv, 1536, wqkv_b, nullptr, 0, DD, 0);

    // 2. RoPE + head split (stores rounded)
    rope_kernel<<<(BB*NN*HH*32 + 255)/256, 256>>>(freqs);

    // 3. Attention (tf32 tensor cores)
    attn_tc<<<dim3(NN/128, BB*HH), 256, ATT_SMEM>>>();

    // 4. hcat left half = round(x)
    copy_x_kernel<<<(MROWS*128 + 255)/256, 256>>>(x);

    // 5. out-proj into hcat right half (rounded): [8192,512]@[512,512]
    gemm_tf32<<<dim3(512/GBN, MROWS/GBM), 256>>>(
        p_attn, DD, p_wr + WOFF_OUT, DD, p_hcat + 512, 1024, out_b, nullptr, 0, DD, 1);

    // 6. FFN1: [8192,1024]@[1024,1024]
    gemm_tf32<<<dim3(1024/GBN, MROWS/GBM), 256>>>(
        p_hcat, 1024, p_wr + WOFF_FFN1, 1024, p_h1, 1024, ffn1_b, nullptr, 0, 1024, 0);

    // 7. LayerNorm + exact GELU (in place, stores rounded)
    ln_gelu_kernel<<<MROWS, 256>>>(ln_g, ln_b);

    // 8. FFN2 + residual: out = x + h1 @ [1024,512] + b
    gemm_tf32<<<dim3(512/GBN, MROWS/GBM), 256>>>(
        p_h1, 1024, p_wr + WOFF_FFN2, DD, out, DD, ffn2_b, x, DD, 1024, 0);
}